// round 11
// baseline (speedup 1.0000x reference)
#include <cuda_runtime.h>
#include <cuda_fp16.h>
#include <cstdint>

// ============================================================================
// y[128, 11008] = x[128,4096] @ W[11008,4096]^T * scale + bias
// w_q arrives as int32 (harness widens int8 -> int32).
// fp16 single-pass: x -> fp16 (rel err ~2e-4), W int8 exact in fp16.
// mma.sync.m16n8k16 + ldmatrix fragments.
// R10: fat warp tiles. CTA 64(M) x 80(N), 128 threads (2x2 warps, warp tile
// 32x40), grid 276, 2 CTAs/SM, NSTAGES=2. Cuts ldmatrix traffic 1.67x.
// ============================================================================

#define M_ROWS 128
#define M_TILE 64
#define K_DIM  4096
#define N_DIM  11008
#define N_TILE 80
#define N_COLS 138
#define N_BLOCKS (2 * N_COLS)              // 276
#define K_STAGE 128                        // k elements per stage
#define NSTAGES 2
#define NUM_STEPS (K_DIM / K_STAGE)        // 32
#define NTHREADS 128

#define SMEM_ROW 272                       // 256B data + 16 pad
#define A_TILE_BYTES (M_TILE * SMEM_ROW)   // 17408
#define B_TILE_BYTES (N_TILE * SMEM_ROW)   // 21760
#define STAGE_BYTES  (A_TILE_BYTES + B_TILE_BYTES)       // 39168
#define SMEM_TOTAL   (NSTAGES * STAGE_BYTES)             // 78336 -> 2 CTAs/SM

#define B_OFF  A_TILE_BYTES

// ---- scratch (no cudaMalloc allowed) ----
__device__ __align__(1024) __half g_xh[M_ROWS * K_DIM];

// ============================================================================
// helpers
// ============================================================================
__device__ __forceinline__ uint32_t smem_u32(const void* p) {
    uint32_t a;
    asm("{ .reg .u64 t; cvta.to.shared.u64 t, %1; cvt.u32.u64 %0, t; }"
        : "=r"(a) : "l"(p));
    return a;
}
__device__ __forceinline__ void cp16(uint32_t dst, const void* src) {
    asm volatile("cp.async.cg.shared.global [%0], [%1], 16;"
                 :: "r"(dst), "l"(src) : "memory");
}
__device__ __forceinline__ void cp_commit() {
    asm volatile("cp.async.commit_group;" ::: "memory");
}
template <int N>
__device__ __forceinline__ void cp_wait() {
    asm volatile("cp.async.wait_group %0;" :: "n"(N) : "memory");
}
__device__ __forceinline__ void ldsm_x4(uint32_t* r, uint32_t addr) {
    asm volatile("ldmatrix.sync.aligned.m8n8.x4.shared.b16 {%0,%1,%2,%3}, [%4];"
                 : "=r"(r[0]), "=r"(r[1]), "=r"(r[2]), "=r"(r[3]) : "r"(addr));
}
__device__ __forceinline__ void ldsm_x2(uint32_t* r, uint32_t addr) {
    asm volatile("ldmatrix.sync.aligned.m8n8.x2.shared.b16 {%0,%1}, [%2];"
                 : "=r"(r[0]), "=r"(r[1]) : "r"(addr));
}
__device__ __forceinline__ void mma_f16(float* d, const uint32_t* a, const uint32_t* b) {
    asm volatile(
        "mma.sync.aligned.m16n8k16.row.col.f32.f16.f16.f32 "
        "{%0,%1,%2,%3}, {%4,%5,%6,%7}, {%8,%9}, {%0,%1,%2,%3};"
        : "+f"(d[0]), "+f"(d[1]), "+f"(d[2]), "+f"(d[3])
        : "r"(a[0]), "r"(a[1]), "r"(a[2]), "r"(a[3]), "r"(b[0]), "r"(b[1]));
}
__device__ __forceinline__ uint32_t i2h2(int lo, int hi) {
    __half2 h = __halves2half2(__int2half_rn(lo), __int2half_rn(hi));
    return *reinterpret_cast<uint32_t*>(&h);
}

// ============================================================================
// Kernel 1: x (fp32) -> fp16
// ============================================================================
__global__ __launch_bounds__(512) void cvt_x_kernel(const float* __restrict__ x) {
    int idx = (blockIdx.x * 512 + threadIdx.x) * 8;
    float4 v0 = *reinterpret_cast<const float4*>(x + idx);
    float4 v1 = *reinterpret_cast<const float4*>(x + idx + 4);
    __half2 h[4];
    h[0] = __floats2half2_rn(v0.x, v0.y);
    h[1] = __floats2half2_rn(v0.z, v0.w);
    h[2] = __floats2half2_rn(v1.x, v1.y);
    h[3] = __floats2half2_rn(v1.z, v1.w);
    *reinterpret_cast<uint4*>(g_xh + idx) = *reinterpret_cast<uint4*>(h);
}

// ============================================================================
// Kernel 2: GEMM. 276 CTAs x 128 threads, 2 CTAs/SM. CTA tile 64(M) x 80(N).
// 2x2 warp grid, warp tile 32x40 (10 MMAs per k16 per warp).
// B path per thread: 20 rows (wr+4j), LDG chunks at ks0-4, pack at ks2-6,
// held packed regs -> STS(s+1) right after the step barrier.
// ============================================================================
__global__ void __launch_bounds__(NTHREADS, 2) gemm_f16_kernel(
    const int* __restrict__ w32,
    const float* __restrict__ scale,
    const float* __restrict__ bias,
    float* __restrict__ out)
{
    extern __shared__ char smem[];
    const uint32_t sb = smem_u32(smem);
    const int tid = threadIdx.x;
    const int lane = tid & 31;
    const int wid = tid >> 5;
    const int wm = wid & 1;        // warp M index (0..1)
    const int wn = wid >> 1;       // warp N index (0..1)
    const int bx = blockIdx.x;
    const int n_base = (bx >> 1) * N_TILE;
    const int m_base = (bx & 1) * M_TILE;

    // ---- A-side cp.async: 128 threads x 8 x 16B per stage ------------------
    uint32_t cpA_dst[8];
    const __half* cpA_src[8];
#pragma unroll
    for (int i = 0; i < 8; i++) {
        int c = tid + i * 128;           // [0, 1024)
        int r = c >> 4;                  // m row 0..63
        int col = (c & 15) * 16;         // byte col 0..240
        cpA_dst[i] = sb + r * SMEM_ROW + col;
        cpA_src[i] = g_xh + (size_t)(m_base + r) * K_DIM + col / 2;
    }
    auto issueA = [&](int s) {
        uint32_t buf_off = (uint32_t)((s & (NSTAGES - 1)) * STAGE_BYTES);
        int k0 = s * K_STAGE;
#pragma unroll
        for (int i = 0; i < 8; i++)
            cp16(cpA_dst[i] + buf_off, cpA_src[i] + k0);
        cp_commit();
    };

    // ---- B-side: 20 rows per thread (wr + 4j), k = lane*4 ------------------
    const int wr = tid >> 5;            // 0..3
    const int klane = lane * 4;         // int32 index within W row
    int4 raw[5][4];                     // 5 chunks x 4 rows (transient)
    uint2 pk[20];                       // packed fp16, held across step

    auto ldg_chunk = [&](int s, int c) {
        const int k0 = s * K_STAGE + klane;
#pragma unroll
        for (int j = 0; j < 4; j++) {
            int rg = n_base + wr + 4 * (c * 4 + j);
            if (rg > N_DIM - 1) rg = N_DIM - 1;   // clamp (ragged last column)
            raw[c][j] = *reinterpret_cast<const int4*>(w32 + (size_t)rg * K_DIM + k0);
        }
    };
    auto pack_chunk = [&](int c) {
#pragma unroll
        for (int j = 0; j < 4; j++) {
            pk[c * 4 + j].x = i2h2(raw[c][j].x, raw[c][j].y);
            pk[c * 4 + j].y = i2h2(raw[c][j].z, raw[c][j].w);
        }
    };
    auto stsB = [&](int s) {
        char* dst = smem + (s & (NSTAGES - 1)) * STAGE_BYTES + B_OFF
                         + wr * SMEM_ROW + lane * 8;
#pragma unroll
        for (int j = 0; j < 20; j++)
            *reinterpret_cast<uint2*>(dst + j * 4 * SMEM_ROW) = pk[j];
    };

    // ---- prologue: B(0) to smem, B(1) packed in regs, A(0) in flight -------
#pragma unroll
    for (int c = 0; c < 5; c++) { ldg_chunk(0, c); pack_chunk(c); }
    stsB(0);
#pragma unroll
    for (int c = 0; c < 5; c++) { ldg_chunk(1, c); pack_chunk(c); }
    issueA(0);

    // ---- ldmatrix per-lane addresses ---------------------------------------
    const int aRow  = lane & 15;
    const int aKoff = (lane >> 4) * 16;
    const int bRow  = (lane & 7) | ((lane >> 4) << 3);
    const int bKoff = ((lane >> 3) & 1) * 16;
    const uint32_t aAddr = sb + (uint32_t)((wm * 32 + aRow) * SMEM_ROW + aKoff);
    const uint32_t bAddr = sb + (uint32_t)B_OFF
                         + (uint32_t)((wn * 40 + bRow) * SMEM_ROW + bKoff);
    // x2 (n-octet 4, cols 32-39): lanes 0-7 -> k0-7, lanes 8-15 -> k8-15
    const uint32_t bAddr2 = sb + (uint32_t)B_OFF
                          + (uint32_t)((wn * 40 + 32 + (lane & 7)) * SMEM_ROW
                                       + ((lane >> 3) & 1) * 16);

    float acc[2][5][4] = {};
    uint32_t afc[2][4], bfc[10], afn[2][4], bfn[10];

    auto load_frags = [&](uint32_t* a0, uint32_t* a1, uint32_t* b, uint32_t off) {
        ldsm_x4(a0, aAddr + off);
        ldsm_x4(a1, aAddr + off + 16 * SMEM_ROW);
        ldsm_x4(b,     bAddr + off);
        ldsm_x4(b + 4, bAddr + off + 16 * SMEM_ROW);
        ldsm_x2(b + 8, bAddr2 + off);
    };

    // ---- main loop ---------------------------------------------------------
    for (int s = 0; s < NUM_STEPS; s++) {
        cp_wait<0>();          // A(s) landed
        __syncthreads();       // publish A(s) + everyone's B(s)

        if (s + 1 < NUM_STEPS) { stsB(s + 1); issueA(s + 1); }

        const uint32_t buf = (uint32_t)((s & (NSTAGES - 1)) * STAGE_BYTES);
        load_frags(afc[0], afc[1], bfc, buf);

#pragma unroll
        for (int ks = 0; ks < 8; ks++) {          // 8 x k16 per stage
            if (ks < 7)
                load_frags(afn[0], afn[1], bfn, buf + (ks + 1) * 32);

            // B(s+2): LDG chunks at ks0-4, pack at ks2-6 (distance-2)
            if (s + 2 < NUM_STEPS) {
                if (ks <= 4) ldg_chunk(s + 2, ks);
                if (ks >= 2 && ks <= 6) pack_chunk(ks - 2);
            }

#pragma unroll
            for (int mf = 0; mf < 2; mf++)
#pragma unroll
                for (int j = 0; j < 5; j++)
                    mma_f16(acc[mf][j], afc[mf], bfc + 2 * j);

            if (ks < 7) {
#pragma unroll
                for (int r = 0; r < 4; r++) { afc[0][r] = afn[0][r]; afc[1][r] = afn[1][r]; }
#pragma unroll
                for (int r = 0; r < 10; r++) bfc[r] = bfn[r];
            }
        }
    }

    // ---- epilogue ----------------------------------------------------------
    const float sw = __ldg(scale);
    const int g = lane >> 2;
    const int mrow0 = m_base + wm * 32 + g;
#pragma unroll
    for (int mf = 0; mf < 2; mf++) {
        int m0 = mrow0 + mf * 16;
#pragma unroll
        for (int j = 0; j < 5; j++) {
            int n = n_base + wn * 40 + j * 8 + 2 * (lane & 3);
            if (n < N_DIM) {
                float2 bv = __ldg(reinterpret_cast<const float2*>(bias + n));
                float2 o0, o1;
                o0.x = acc[mf][j][0] * sw + bv.x;
                o0.y = acc[mf][j][1] * sw + bv.y;
                o1.x = acc[mf][j][2] * sw + bv.x;
                o1.y = acc[mf][j][3] * sw + bv.y;
                *reinterpret_cast<float2*>(out + (size_t)m0 * N_DIM + n) = o0;
                *reinterpret_cast<float2*>(out + (size_t)(m0 + 8) * N_DIM + n) = o1;
            }
        }
    }
}

// ============================================================================
// Host launcher — inputs identified by element count (order-robust)
// ============================================================================
extern "C" void kernel_launch(void* const* d_in, const int* in_sizes, int n_in,
                              void* d_out, int out_size) {
    const float* x     = nullptr;
    const int*   w32   = nullptr;    // int8 weights widened to int32 by harness
    const float* scale = nullptr;
    const float* bias  = nullptr;
    for (int i = 0; i < n_in; i++) {
        switch (in_sizes[i]) {
            case M_ROWS * K_DIM: x     = (const float*)d_in[i]; break;  // 524288
            case N_DIM * K_DIM:  w32   = (const int*)d_in[i];   break;  // 45088768
            case 1:              scale = (const float*)d_in[i]; break;
            case N_DIM:          bias  = (const float*)d_in[i]; break;  // 11008
        }
    }
    float* out = (float*)d_out;

    cudaFuncSetAttribute(gemm_f16_kernel,
                         cudaFuncAttributeMaxDynamicSharedMemorySize, SMEM_TOTAL);

    cvt_x_kernel<<<M_ROWS, 512>>>(x);
    gemm_f16_kernel<<<N_BLOCKS, NTHREADS, SMEM_TOTAL>>>(w32, scale, bias, out);
}

// round 12
// speedup vs baseline: 1.0430x; 1.0430x over previous
#include <cuda_runtime.h>
#include <cuda_fp16.h>
#include <cstdint>

// ============================================================================
// y[128, 11008] = x[128,4096] @ W[11008,4096]^T * scale + bias
// w_q arrives as int32 (harness widens int8 -> int32).
// fp16 single-pass: x -> fp16 (rel err ~2e-4), W int8 exact in fp16.
// mma.sync.m16n8k16 + ldmatrix fragments.
// R11: R10 fat tiles (CTA 64x80, 128 thr, warp tile 32x40, 2 CTAs/SM) with
// register discipline: B raw ring-3 (48 regs vs 80) -> no spills.
// B schedule: ldg(c)@ks=c (0-4), pack(c)@ks=c+2 (2-6), STS(s+1) after sync.
// ============================================================================

#define M_ROWS 128
#define M_TILE 64
#define K_DIM  4096
#define N_DIM  11008
#define N_TILE 80
#define N_COLS 138
#define N_BLOCKS (2 * N_COLS)              // 276
#define K_STAGE 128                        // k elements per stage
#define NSTAGES 2
#define NUM_STEPS (K_DIM / K_STAGE)        // 32
#define NTHREADS 128

#define SMEM_ROW 272                       // 256B data + 16 pad
#define A_TILE_BYTES (M_TILE * SMEM_ROW)   // 17408
#define B_TILE_BYTES (N_TILE * SMEM_ROW)   // 21760
#define STAGE_BYTES  (A_TILE_BYTES + B_TILE_BYTES)       // 39168
#define SMEM_TOTAL   (NSTAGES * STAGE_BYTES)             // 78336 -> 2 CTAs/SM

#define B_OFF  A_TILE_BYTES

// ---- scratch (no cudaMalloc allowed) ----
__device__ __align__(1024) __half g_xh[M_ROWS * K_DIM];

// ============================================================================
// helpers
// ============================================================================
__device__ __forceinline__ uint32_t smem_u32(const void* p) {
    uint32_t a;
    asm("{ .reg .u64 t; cvta.to.shared.u64 t, %1; cvt.u32.u64 %0, t; }"
        : "=r"(a) : "l"(p));
    return a;
}
__device__ __forceinline__ void cp16(uint32_t dst, const void* src) {
    asm volatile("cp.async.cg.shared.global [%0], [%1], 16;"
                 :: "r"(dst), "l"(src) : "memory");
}
__device__ __forceinline__ void cp_commit() {
    asm volatile("cp.async.commit_group;" ::: "memory");
}
template <int N>
__device__ __forceinline__ void cp_wait() {
    asm volatile("cp.async.wait_group %0;" :: "n"(N) : "memory");
}
__device__ __forceinline__ void ldsm_x4(uint32_t* r, uint32_t addr) {
    asm volatile("ldmatrix.sync.aligned.m8n8.x4.shared.b16 {%0,%1,%2,%3}, [%4];"
                 : "=r"(r[0]), "=r"(r[1]), "=r"(r[2]), "=r"(r[3]) : "r"(addr));
}
__device__ __forceinline__ void ldsm_x2(uint32_t* r, uint32_t addr) {
    asm volatile("ldmatrix.sync.aligned.m8n8.x2.shared.b16 {%0,%1}, [%2];"
                 : "=r"(r[0]), "=r"(r[1]) : "r"(addr));
}
__device__ __forceinline__ void mma_f16(float* d, const uint32_t* a, const uint32_t* b) {
    asm volatile(
        "mma.sync.aligned.m16n8k16.row.col.f32.f16.f16.f32 "
        "{%0,%1,%2,%3}, {%4,%5,%6,%7}, {%8,%9}, {%0,%1,%2,%3};"
        : "+f"(d[0]), "+f"(d[1]), "+f"(d[2]), "+f"(d[3])
        : "r"(a[0]), "r"(a[1]), "r"(a[2]), "r"(a[3]), "r"(b[0]), "r"(b[1]));
}
__device__ __forceinline__ uint32_t i2h2(int lo, int hi) {
    __half2 h = __halves2half2(__int2half_rn(lo), __int2half_rn(hi));
    return *reinterpret_cast<uint32_t*>(&h);
}

// ============================================================================
// Kernel 1: x (fp32) -> fp16
// ============================================================================
__global__ __launch_bounds__(512) void cvt_x_kernel(const float* __restrict__ x) {
    int idx = (blockIdx.x * 512 + threadIdx.x) * 8;
    float4 v0 = *reinterpret_cast<const float4*>(x + idx);
    float4 v1 = *reinterpret_cast<const float4*>(x + idx + 4);
    __half2 h[4];
    h[0] = __floats2half2_rn(v0.x, v0.y);
    h[1] = __floats2half2_rn(v0.z, v0.w);
    h[2] = __floats2half2_rn(v1.x, v1.y);
    h[3] = __floats2half2_rn(v1.z, v1.w);
    *reinterpret_cast<uint4*>(g_xh + idx) = *reinterpret_cast<uint4*>(h);
}

// ============================================================================
// Kernel 2: GEMM. 276 CTAs x 128 threads, 2 CTAs/SM. CTA tile 64(M) x 80(N).
// 2x2 warp grid, warp tile 32x40 (10 MMAs per k16 per warp).
// ============================================================================
__global__ void __launch_bounds__(NTHREADS, 2) gemm_f16_kernel(
    const int* __restrict__ w32,
    const float* __restrict__ scale,
    const float* __restrict__ bias,
    float* __restrict__ out)
{
    extern __shared__ char smem[];
    const uint32_t sb = smem_u32(smem);
    const int tid = threadIdx.x;
    const int lane = tid & 31;
    const int wid = tid >> 5;
    const int wm = wid & 1;        // warp M index (0..1)
    const int wn = wid >> 1;       // warp N index (0..1)
    const int bx = blockIdx.x;
    const int n_base = (bx >> 1) * N_TILE;
    const int m_base = (bx & 1) * M_TILE;

    // ---- A-side cp.async: 128 threads x 8 x 16B per stage ------------------
    uint32_t cpA_dst[8];
    const __half* cpA_src[8];
#pragma unroll
    for (int i = 0; i < 8; i++) {
        int c = tid + i * 128;           // [0, 1024)
        int r = c >> 4;                  // m row 0..63
        int col = (c & 15) * 16;         // byte col 0..240
        cpA_dst[i] = sb + r * SMEM_ROW + col;
        cpA_src[i] = g_xh + (size_t)(m_base + r) * K_DIM + col / 2;
    }
    auto issueA = [&](int s) {
        uint32_t buf_off = (uint32_t)((s & (NSTAGES - 1)) * STAGE_BYTES);
        int k0 = s * K_STAGE;
#pragma unroll
        for (int i = 0; i < 8; i++)
            cp16(cpA_dst[i] + buf_off, cpA_src[i] + k0);
        cp_commit();
    };

    // ---- B-side: 20 rows per thread (wr + 4j), k = lane*4 ------------------
    // raw ring of 3 chunk-buffers (48 regs): ldg(c)->raw[c%3], pack(c) 2 later.
    const int wr = tid >> 5;            // 0..3
    const int klane = lane * 4;         // int32 index within W row
    int4 raw[3][4];
    uint2 pk[20];                       // packed fp16, held across step

    auto ldg_chunk = [&](int s, int c) {
        const int k0 = s * K_STAGE + klane;
        int4* r = raw[c % 3];
#pragma unroll
        for (int j = 0; j < 4; j++) {
            int rg = n_base + wr + 4 * (c * 4 + j);
            if (rg > N_DIM - 1) rg = N_DIM - 1;   // clamp (ragged last column)
            r[j] = *reinterpret_cast<const int4*>(w32 + (size_t)rg * K_DIM + k0);
        }
    };
    auto pack_chunk = [&](int c) {
        const int4* r = raw[c % 3];
#pragma unroll
        for (int j = 0; j < 4; j++) {
            pk[c * 4 + j].x = i2h2(r[j].x, r[j].y);
            pk[c * 4 + j].y = i2h2(r[j].z, r[j].w);
        }
    };
    auto stsB = [&](int s) {
        char* dst = smem + (s & (NSTAGES - 1)) * STAGE_BYTES + B_OFF
                         + wr * SMEM_ROW + lane * 8;
#pragma unroll
        for (int j = 0; j < 20; j++)
            *reinterpret_cast<uint2*>(dst + j * 4 * SMEM_ROW) = pk[j];
    };

    // ---- prologue: B(0) to smem, B(1) packed in regs, A(0) in flight -------
#pragma unroll
    for (int c = 0; c < 5; c++) { ldg_chunk(0, c); pack_chunk(c); }
    stsB(0);
#pragma unroll
    for (int c = 0; c < 5; c++) { ldg_chunk(1, c); pack_chunk(c); }
    issueA(0);

    // ---- ldmatrix per-lane addresses ---------------------------------------
    const int aRow  = lane & 15;
    const int aKoff = (lane >> 4) * 16;
    const int bRow  = (lane & 7) | ((lane >> 4) << 3);
    const int bKoff = ((lane >> 3) & 1) * 16;
    const uint32_t aAddr = sb + (uint32_t)((wm * 32 + aRow) * SMEM_ROW + aKoff);
    const uint32_t bAddr = sb + (uint32_t)B_OFF
                         + (uint32_t)((wn * 40 + bRow) * SMEM_ROW + bKoff);
    // x2 (n-octet 4, cols 32-39): lanes 0-7 -> k0-7, lanes 8-15 -> k8-15
    const uint32_t bAddr2 = sb + (uint32_t)B_OFF
                          + (uint32_t)((wn * 40 + 32 + (lane & 7)) * SMEM_ROW
                                       + ((lane >> 3) & 1) * 16);

    float acc[2][5][4] = {};
    uint32_t afc[2][4], bfc[10], afn[2][4], bfn[10];

    auto load_frags = [&](uint32_t* a0, uint32_t* a1, uint32_t* b, uint32_t off) {
        ldsm_x4(a0, aAddr + off);
        ldsm_x4(a1, aAddr + off + 16 * SMEM_ROW);
        ldsm_x4(b,     bAddr + off);
        ldsm_x4(b + 4, bAddr + off + 16 * SMEM_ROW);
        ldsm_x2(b + 8, bAddr2 + off);
    };

    // ---- main loop ---------------------------------------------------------
    for (int s = 0; s < NUM_STEPS; s++) {
        cp_wait<0>();          // A(s) landed
        __syncthreads();       // publish A(s) + everyone's B(s)

        if (s + 1 < NUM_STEPS) { stsB(s + 1); issueA(s + 1); }

        const uint32_t buf = (uint32_t)((s & (NSTAGES - 1)) * STAGE_BYTES);
        load_frags(afc[0], afc[1], bfc, buf);

#pragma unroll
        for (int ks = 0; ks < 8; ks++) {          // 8 x k16 per stage
            if (ks < 7)
                load_frags(afn[0], afn[1], bfn, buf + (ks + 1) * 32);

            // B(s+2): ldg(c)@ks=c (0-4), pack(c)@ks=c+2 (2-6); ring-3 safe
            if (s + 2 < NUM_STEPS) {
                if (ks <= 4) ldg_chunk(s + 2, ks);
                if (ks >= 2 && ks <= 6) pack_chunk(ks - 2);
            }

#pragma unroll
            for (int mf = 0; mf < 2; mf++)
#pragma unroll
                for (int j = 0; j < 5; j++)
                    mma_f16(acc[mf][j], afc[mf], bfc + 2 * j);

            if (ks < 7) {
#pragma unroll
                for (int r = 0; r < 4; r++) { afc[0][r] = afn[0][r]; afc[1][r] = afn[1][r]; }
#pragma unroll
                for (int r = 0; r < 10; r++) bfc[r] = bfn[r];
            }
        }
    }

    // ---- epilogue ----------------------------------------------------------
    const float sw = __ldg(scale);
    const int g = lane >> 2;
    const int mrow0 = m_base + wm * 32 + g;
#pragma unroll
    for (int mf = 0; mf < 2; mf++) {
        int m0 = mrow0 + mf * 16;
#pragma unroll
        for (int j = 0; j < 5; j++) {
            int n = n_base + wn * 40 + j * 8 + 2 * (lane & 3);
            if (n < N_DIM) {
                float2 bv = __ldg(reinterpret_cast<const float2*>(bias + n));
                float2 o0, o1;
                o0.x = acc[mf][j][0] * sw + bv.x;
                o0.y = acc[mf][j][1] * sw + bv.y;
                o1.x = acc[mf][j][2] * sw + bv.x;
                o1.y = acc[mf][j][3] * sw + bv.y;
                *reinterpret_cast<float2*>(out + (size_t)m0 * N_DIM + n) = o0;
                *reinterpret_cast<float2*>(out + (size_t)(m0 + 8) * N_DIM + n) = o1;
            }
        }
    }
}

// ============================================================================
// Host launcher — inputs identified by element count (order-robust)
// ============================================================================
extern "C" void kernel_launch(void* const* d_in, const int* in_sizes, int n_in,
                              void* d_out, int out_size) {
    const float* x     = nullptr;
    const int*   w32   = nullptr;    // int8 weights widened to int32 by harness
    const float* scale = nullptr;
    const float* bias  = nullptr;
    for (int i = 0; i < n_in; i++) {
        switch (in_sizes[i]) {
            case M_ROWS * K_DIM: x     = (const float*)d_in[i]; break;  // 524288
            case N_DIM * K_DIM:  w32   = (const int*)d_in[i];   break;  // 45088768
            case 1:              scale = (const float*)d_in[i]; break;
            case N_DIM:          bias  = (const float*)d_in[i]; break;  // 11008
        }
    }
    float* out = (float*)d_out;

    cudaFuncSetAttribute(gemm_f16_kernel,
                         cudaFuncAttributeMaxDynamicSharedMemorySize, SMEM_TOTAL);

    cvt_x_kernel<<<M_ROWS, 512>>>(x);
    gemm_f16_kernel<<<N_BLOCKS, NTHREADS, SMEM_TOTAL>>>(w32, scale, bias, out);
}

// round 14
// speedup vs baseline: 1.3938x; 1.3364x over previous
#include <cuda_runtime.h>
#include <cuda_fp16.h>
#include <cstdint>

// ============================================================================
// y[128, 11008] = x[128,4096] @ W[11008,4096]^T * scale + bias
// w_q arrives as int32 (harness widens int8 -> int32).
// fp16 single-pass: x -> fp16 (rel err ~2e-4), W int8 exact in fp16.
// mma.sync.m16n8k16 + ldmatrix fragments.
// R12: CTA 128(M) x 40(N), 128 thr, 4 warps (4Mx1N), warp tile 32x40.
// Grid 276 (one CTA per n-strip), 2 CTAs/SM, NSTAGES=2, K_STAGE=128.
// Full-M CTAs: W read once (DRAM traffic halved vs M-split).
// B-path register budget identical to proven R9 (raw[5] + pk[10]).
// ============================================================================

#define M_ROWS 128
#define K_DIM  4096
#define N_DIM  11008
#define N_TILE 40
#define N_BLOCKS ((N_DIM + N_TILE - 1) / N_TILE)   // 276
#define K_STAGE 128                        // k elements per stage
#define NSTAGES 2
#define NUM_STEPS (K_DIM / K_STAGE)        // 32
#define NTHREADS 128

#define SMEM_ROW 272                       // 256B data + 16 pad
#define A_TILE_BYTES (M_ROWS * SMEM_ROW)   // 34816
#define B_TILE_BYTES (N_TILE * SMEM_ROW)   // 10880
#define STAGE_BYTES  (A_TILE_BYTES + B_TILE_BYTES)       // 45696
#define SMEM_TOTAL   (NSTAGES * STAGE_BYTES)             // 91392 -> 2 CTAs/SM

#define B_OFF  A_TILE_BYTES

// ---- scratch (no cudaMalloc allowed) ----
__device__ __align__(1024) __half g_xh[M_ROWS * K_DIM];

// ============================================================================
// helpers
// ============================================================================
__device__ __forceinline__ uint32_t smem_u32(const void* p) {
    uint32_t a;
    asm("{ .reg .u64 t; cvta.to.shared.u64 t, %1; cvt.u32.u64 %0, t; }"
        : "=r"(a) : "l"(p));
    return a;
}
__device__ __forceinline__ void cp16(uint32_t dst, const void* src) {
    asm volatile("cp.async.cg.shared.global [%0], [%1], 16;"
                 :: "r"(dst), "l"(src) : "memory");
}
__device__ __forceinline__ void cp_commit() {
    asm volatile("cp.async.commit_group;" ::: "memory");
}
template <int N>
__device__ __forceinline__ void cp_wait() {
    asm volatile("cp.async.wait_group %0;" :: "n"(N) : "memory");
}
__device__ __forceinline__ void ldsm_x4(uint32_t* r, uint32_t addr) {
    asm volatile("ldmatrix.sync.aligned.m8n8.x4.shared.b16 {%0,%1,%2,%3}, [%4];"
                 : "=r"(r[0]), "=r"(r[1]), "=r"(r[2]), "=r"(r[3]) : "r"(addr));
}
__device__ __forceinline__ void ldsm_x2(uint32_t* r, uint32_t addr) {
    asm volatile("ldmatrix.sync.aligned.m8n8.x2.shared.b16 {%0,%1}, [%2];"
                 : "=r"(r[0]), "=r"(r[1]) : "r"(addr));
}
__device__ __forceinline__ void mma_f16(float* d, const uint32_t* a, const uint32_t* b) {
    asm volatile(
        "mma.sync.aligned.m16n8k16.row.col.f32.f16.f16.f32 "
        "{%0,%1,%2,%3}, {%4,%5,%6,%7}, {%8,%9}, {%0,%1,%2,%3};"
        : "+f"(d[0]), "+f"(d[1]), "+f"(d[2]), "+f"(d[3])
        : "r"(a[0]), "r"(a[1]), "r"(a[2]), "r"(a[3]), "r"(b[0]), "r"(b[1]));
}
__device__ __forceinline__ uint32_t i2h2(int lo, int hi) {
    __half2 h = __halves2half2(__int2half_rn(lo), __int2half_rn(hi));
    return *reinterpret_cast<uint32_t*>(&h);
}

// ============================================================================
// Kernel 1: x (fp32) -> fp16
// ============================================================================
__global__ __launch_bounds__(512) void cvt_x_kernel(const float* __restrict__ x) {
    int idx = (blockIdx.x * 512 + threadIdx.x) * 8;
    float4 v0 = *reinterpret_cast<const float4*>(x + idx);
    float4 v1 = *reinterpret_cast<const float4*>(x + idx + 4);
    __half2 h[4];
    h[0] = __floats2half2_rn(v0.x, v0.y);
    h[1] = __floats2half2_rn(v0.z, v0.w);
    h[2] = __floats2half2_rn(v1.x, v1.y);
    h[3] = __floats2half2_rn(v1.z, v1.w);
    *reinterpret_cast<uint4*>(g_xh + idx) = *reinterpret_cast<uint4*>(h);
}

// ============================================================================
// Kernel 2: GEMM. 276 CTAs x 128 threads, 2 CTAs/SM. CTA tile 128(M) x 40(N).
// 4 warps, warp tile 32x40 (10 MMAs per k16 per warp).
// B path per thread: 10 rows (wr + 4j), halves of 5:
//   ldg_h0 after sync; pack_h0 + ldg_h1 @ks2; pack_h1 @ks6; STS(s+1) after
//   next sync (R9-proven schedule, raw[5] transient + pk[10] held).
// ============================================================================
__global__ void __launch_bounds__(NTHREADS, 2) gemm_f16_kernel(
    const int* __restrict__ w32,
    const float* __restrict__ scale,
    const float* __restrict__ bias,
    float* __restrict__ out)
{
    extern __shared__ char smem[];
    const uint32_t sb = smem_u32(smem);
    const int tid = threadIdx.x;
    const int lane = tid & 31;
    const int wid = tid >> 5;          // warp M index (0..3)
    const int n_base = blockIdx.x * N_TILE;

    // ---- A-side cp.async: all 128 threads, 16 x 16B per stage (inline addr) -
    auto issueA = [&](int s) {
        const uint32_t buf = (uint32_t)((s & (NSTAGES - 1)) * STAGE_BYTES);
        const int k0h = s * K_STAGE;     // fp16 element offset
#pragma unroll
        for (int i = 0; i < 16; i++) {
            int c = tid + i * 128;       // [0, 2048)
            int r = c >> 4;              // m row 0..127
            int col = (c & 15) * 16;     // byte col 0..240
            cp16(sb + buf + r * SMEM_ROW + col,
                 g_xh + (size_t)r * K_DIM + k0h + col / 2);
        }
        cp_commit();
    };

    // ---- B-side: 10 rows per thread (wr + 4j), k = lane*4 ------------------
    const int wr = wid;                 // 0..3
    const int klane = lane * 4;         // int32 index within W row
    int4 raw[5];                        // transient half
    uint2 pk[10];                       // packed fp16, held across step

    auto ldg_half = [&](int s, int h) {
        const int k0 = s * K_STAGE + klane;
#pragma unroll
        for (int j = 0; j < 5; j++) {
            int rg = n_base + wr + 4 * (h * 5 + j);
            if (rg > N_DIM - 1) rg = N_DIM - 1;   // clamp (ragged last tile)
            raw[j] = *reinterpret_cast<const int4*>(w32 + (size_t)rg * K_DIM + k0);
        }
    };
    auto pack_half = [&](int h) {
#pragma unroll
        for (int j = 0; j < 5; j++) {
            pk[h * 5 + j].x = i2h2(raw[j].x, raw[j].y);
            pk[h * 5 + j].y = i2h2(raw[j].z, raw[j].w);
        }
    };
    auto stsB = [&](int s) {
        char* dst = smem + (s & (NSTAGES - 1)) * STAGE_BYTES + B_OFF
                         + wr * SMEM_ROW + lane * 8;
#pragma unroll
        for (int j = 0; j < 10; j++)
            *reinterpret_cast<uint2*>(dst + j * 4 * SMEM_ROW) = pk[j];
    };

    // ---- prologue: B(0) to smem, B(1) packed in regs, A(0) in flight -------
    ldg_half(0, 0); pack_half(0);
    ldg_half(0, 1); pack_half(1);
    stsB(0);
    ldg_half(1, 0); pack_half(0);
    ldg_half(1, 1); pack_half(1);
    issueA(0);

    // ---- ldmatrix per-lane addresses ---------------------------------------
    const int aRow  = lane & 15;
    const int aKoff = (lane >> 4) * 16;
    const int bRow  = (lane & 7) | ((lane >> 4) << 3);
    const int bKoff = ((lane >> 3) & 1) * 16;
    const uint32_t aAddr = sb + (uint32_t)((wid * 32 + aRow) * SMEM_ROW + aKoff);
    const uint32_t bAddr = sb + (uint32_t)B_OFF
                         + (uint32_t)(bRow * SMEM_ROW + bKoff);
    // x2 (n-octet 4, rows 32-39): lanes 0-7 -> k0-7, lanes 8-15 -> k8-15
    const uint32_t bAddr2 = sb + (uint32_t)B_OFF
                          + (uint32_t)((32 + (lane & 7)) * SMEM_ROW
                                       + ((lane >> 3) & 1) * 16);

    float acc[2][5][4] = {};
    uint32_t afc[2][4], bfc[10], afn[2][4], bfn[10];

    auto load_frags = [&](uint32_t* a0, uint32_t* a1, uint32_t* b, uint32_t off) {
        ldsm_x4(a0, aAddr + off);
        ldsm_x4(a1, aAddr + off + 16 * SMEM_ROW);
        ldsm_x4(b,     bAddr + off);
        ldsm_x4(b + 4, bAddr + off + 16 * SMEM_ROW);
        ldsm_x2(b + 8, bAddr2 + off);
    };

    // ---- main loop ---------------------------------------------------------
    for (int s = 0; s < NUM_STEPS; s++) {
        cp_wait<0>();          // A(s) landed
        __syncthreads();       // publish A(s) + everyone's B(s)

        if (s + 1 < NUM_STEPS) { stsB(s + 1); issueA(s + 1); }
        if (s + 2 < NUM_STEPS) ldg_half(s + 2, 0);

        const uint32_t buf = (uint32_t)((s & (NSTAGES - 1)) * STAGE_BYTES);
        load_frags(afc[0], afc[1], bfc, buf);

#pragma unroll
        for (int ks = 0; ks < 8; ks++) {          // 8 x k16 per stage
            if (ks < 7)
                load_frags(afn[0], afn[1], bfn, buf + (ks + 1) * 32);

            // B(s+2): pack_h0 + ldg_h1 @ks2, pack_h1 @ks6 (R9-proven spacing)
            if (s + 2 < NUM_STEPS) {
                if (ks == 2) { pack_half(0); ldg_half(s + 2, 1); }
                if (ks == 6) pack_half(1);
            }

#pragma unroll
            for (int mf = 0; mf < 2; mf++)
#pragma unroll
                for (int j = 0; j < 5; j++)
                    mma_f16(acc[mf][j], afc[mf], bfc + 2 * j);

            if (ks < 7) {
#pragma unroll
                for (int r = 0; r < 4; r++) { afc[0][r] = afn[0][r]; afc[1][r] = afn[1][r]; }
#pragma unroll
                for (int r = 0; r < 10; r++) bfc[r] = bfn[r];
            }
        }
    }

    // ---- epilogue ----------------------------------------------------------
    const float sw = __ldg(scale);
    const int g = lane >> 2;
    const int mrow0 = wid * 32 + g;
#pragma unroll
    for (int mf = 0; mf < 2; mf++) {
        int m0 = mrow0 + mf * 16;
#pragma unroll
        for (int j = 0; j < 5; j++) {
            int n = n_base + j * 8 + 2 * (lane & 3);
            if (n < N_DIM) {
                float2 bv = __ldg(reinterpret_cast<const float2*>(bias + n));
                float2 o0, o1;
                o0.x = acc[mf][j][0] * sw + bv.x;
                o0.y = acc[mf][j][1] * sw + bv.y;
                o1.x = acc[mf][j][2] * sw + bv.x;
                o1.y = acc[mf][j][3] * sw + bv.y;
                *reinterpret_cast<float2*>(out + (size_t)m0 * N_DIM + n) = o0;
                *reinterpret_cast<float2*>(out + (size_t)(m0 + 8) * N_DIM + n) = o1;
            }
        }
    }
}

// ============================================================================
// Host launcher — inputs identified by element count (order-robust)
// ============================================================================
extern "C" void kernel_launch(void* const* d_in, const int* in_sizes, int n_in,
                              void* d_out, int out_size) {
    const float* x     = nullptr;
    const int*   w32   = nullptr;    // int8 weights widened to int32 by harness
    const float* scale = nullptr;
    const float* bias  = nullptr;
    for (int i = 0; i < n_in; i++) {
        switch (in_sizes[i]) {
            case M_ROWS * K_DIM: x     = (const float*)d_in[i]; break;  // 524288
            case N_DIM * K_DIM:  w32   = (const int*)d_in[i];   break;  // 45088768
            case 1:              scale = (const float*)d_in[i]; break;
            case N_DIM:          bias  = (const float*)d_in[i]; break;  // 11008
        }
    }
    float* out = (float*)d_out;

    cudaFuncSetAttribute(gemm_f16_kernel,
                         cudaFuncAttributeMaxDynamicSharedMemorySize, SMEM_TOTAL);

    cvt_x_kernel<<<M_ROWS, 512>>>(x);
    gemm_f16_kernel<<<N_BLOCKS, NTHREADS, SMEM_TOTAL>>>(w32, scale, bias, out);
}